// round 11
// baseline (speedup 1.0000x reference)
#include <cuda_runtime.h>
#include <math.h>

// ---------------- scratch (static device globals; no allocation) ----------------
__device__ float g_cnn[32768 * 128];     // CNN output per frame
__device__ float g_xg[32768 * 512];      // precomputed x @ enc_w_ih^T + enc_b
__device__ float g_hdec[10][1024 * 128]; // decoder h history for output head

#define WPAD 132   // weight row pad: 132 % 32 == 4 (conflict-free LDS.128 phases)
#define BPAD 68    // 68 % 32 == 4

__device__ __forceinline__ void fma2(unsigned long long& d,
                                     unsigned long long a, unsigned long long b) {
    asm("fma.rn.f32x2 %0, %1, %2, %0;" : "+l"(d) : "l"(a), "l"(b));
}
__device__ __forceinline__ unsigned long long pack2(float v) {
    unsigned long long r;
    asm("mov.b64 %0, {%1, %1};" : "=l"(r) : "f"(v));
    return r;
}
__device__ __forceinline__ unsigned long long packab(float a, float b) {
    unsigned long long r;
    asm("mov.b64 %0, {%1, %2};" : "=l"(r) : "f"(a), "f"(b));
    return r;
}
__device__ __forceinline__ float ulo(unsigned long long v) {
    return __uint_as_float((unsigned)(v & 0xffffffffull));
}
__device__ __forceinline__ float uhi(unsigned long long v) {
    return __uint_as_float((unsigned)(v >> 32));
}
__device__ __forceinline__ float f2sum(unsigned long long v) { return ulo(v) + uhi(v); }
__device__ __forceinline__ unsigned smem_u32(const void* p) {
    unsigned a;
    asm("{ .reg .u64 t; cvta.to.shared.u64 t, %1; cvt.u32.u64 %0, t; }" : "=r"(a) : "l"(p));
    return a;
}

// ---------------- CNN: persistent, frame-pair packed f32x2 (unchanged) ----------------
#define FPB 4
#define IRS 50
#define CNN_GRID 592
__global__ void __launch_bounds__(128) cnn_kernel(
    const float* __restrict__ obs,
    const float* __restrict__ w1, const float* __restrict__ b1,
    const float* __restrict__ w2, const float* __restrict__ b2)
{
    __shared__ float s_ini[4 * 12 * IRS];
    __shared__ float s_p1i[16 * 7 * 2 * 16];
    __shared__ float s_w1[576];
    __shared__ float s_b1[16];
    __shared__ float s_w2t[144 * 33];
    __shared__ float s_b2[32];

    int tid = threadIdx.x; // 128
    for (int i = tid; i < 4 * 12 * IRS; i += 128) s_ini[i] = 0.f;
    for (int i = tid; i < 16 * 7 * 2 * 16; i += 128) s_p1i[i] = 0.f;
    for (int i = tid; i < 576; i += 128) s_w1[i] = w1[i];
    if (tid < 16) s_b1[tid] = b1[tid];
    for (int i = tid; i < 4608; i += 128) {
        int oc = i / 144, r = i % 144;
        s_w2t[r * 33 + oc] = w2[i];
    }
    if (tid < 32) s_b2[tid] = b2[tid];
    __syncthreads();

    for (long f0 = (long)blockIdx.x * FPB; f0 < 32768; f0 += (long)gridDim.x * FPB) {
        for (int i = tid; i < FPB * 400; i += 128) {
            int f = i / 400, rem = i % 400;
            int ic = rem / 100, p = rem % 100, y = p / 10, x = p % 10;
            s_ini[(ic * 12 + y + 1) * IRS + (x + 1) * 4 + f] = obs[f0 * 400 + i];
        }
        __syncthreads();

        if (tid < 100) {
            int fp = tid / 50, rem = tid % 50, ocg = rem / 25, pos = rem % 25;
            int py = pos / 5, px = pos % 5;
            unsigned long long acc2[8][4];
#pragma unroll
            for (int o = 0; o < 8; o++) {
                unsigned long long bp = pack2(s_b1[ocg * 8 + o]);
#pragma unroll
                for (int p = 0; p < 4; p++) acc2[o][p] = bp;
            }
#pragma unroll
            for (int ic = 0; ic < 4; ic++) {
                unsigned long long patch2[4][4];
#pragma unroll
                for (int r = 0; r < 4; r++)
#pragma unroll
                    for (int cc = 0; cc < 4; cc++)
                        patch2[r][cc] = *(const unsigned long long*)
                            &s_ini[(ic * 12 + 2 * py + r) * IRS + (2 * px + cc) * 4 + fp * 2];
#pragma unroll
                for (int o = 0; o < 8; o++) {
                    int oc = ocg * 8 + o;
#pragma unroll
                    for (int ky = 0; ky < 3; ky++)
#pragma unroll
                        for (int kx = 0; kx < 3; kx++) {
                            unsigned long long wp = pack2(s_w1[(oc * 4 + ic) * 9 + ky * 3 + kx]);
                            fma2(acc2[o][0], patch2[ky][kx], wp);
                            fma2(acc2[o][1], patch2[ky][kx + 1], wp);
                            fma2(acc2[o][2], patch2[ky + 1][kx], wp);
                            fma2(acc2[o][3], patch2[ky + 1][kx + 1], wp);
                        }
                }
            }
#pragma unroll
            for (int o = 0; o < 8; o++) {
                int oc = ocg * 8 + o;
                float mlo = fmaxf(fmaxf(ulo(acc2[o][0]), ulo(acc2[o][1])),
                                  fmaxf(ulo(acc2[o][2]), ulo(acc2[o][3])));
                float mhi = fmaxf(fmaxf(uhi(acc2[o][0]), uhi(acc2[o][1])),
                                  fmaxf(uhi(acc2[o][2]), uhi(acc2[o][3])));
                unsigned long long pk = packab(fmaxf(mlo, 0.f), fmaxf(mhi, 0.f));
                int idx = ((oc * 7 + py + 1) * 2 + fp) * 16 + (px + 1) * 2;
                *(unsigned long long*)&s_p1i[idx] = pk;
            }
        }
        __syncthreads();

        {
            int half = tid >> 6, fp = (tid >> 5) & 1, oc = tid & 31;
            unsigned long long acc2[2][4];
            unsigned long long bp = pack2(s_b2[oc]);
#pragma unroll
            for (int yl = 0; yl < 2; yl++)
#pragma unroll
                for (int x = 0; x < 4; x++) acc2[yl][x] = bp;

            for (int ic = 0; ic < 16; ic++) {
                unsigned long long in2[4][6];
#pragma unroll
                for (int rl = 0; rl < 4; rl++)
#pragma unroll
                    for (int cp = 0; cp < 3; cp++) {
                        ulonglong2 v = *(const ulonglong2*)
                            &s_p1i[((ic * 7 + 2 * half + rl) * 2 + fp) * 16 + cp * 4];
                        in2[rl][2 * cp] = v.x;
                        in2[rl][2 * cp + 1] = v.y;
                    }
#pragma unroll
                for (int ky = 0; ky < 3; ky++)
#pragma unroll
                    for (int kx = 0; kx < 3; kx++) {
                        unsigned long long wp = pack2(s_w2t[(ic * 9 + ky * 3 + kx) * 33 + oc]);
#pragma unroll
                        for (int yl = 0; yl < 2; yl++)
#pragma unroll
                            for (int x = 0; x < 4; x++)
                                fma2(acc2[yl][x], in2[yl + ky][x + kx], wp);
                    }
            }
#pragma unroll
            for (int px = 0; px < 2; px++) {
                float mlo = fmaxf(fmaxf(ulo(acc2[0][2 * px]), ulo(acc2[0][2 * px + 1])),
                                  fmaxf(ulo(acc2[1][2 * px]), ulo(acc2[1][2 * px + 1])));
                float mhi = fmaxf(fmaxf(uhi(acc2[0][2 * px]), uhi(acc2[0][2 * px + 1])),
                                  fmaxf(uhi(acc2[1][2 * px]), uhi(acc2[1][2 * px + 1])));
                long fr = f0 + fp * 2;
                g_cnn[fr * 128 + oc * 4 + half * 2 + px] = fmaxf(mlo, 0.f);
                g_cnn[(fr + 1) * 128 + oc * 4 + half * 2 + px] = fmaxf(mhi, 0.f);
            }
        }
        __syncthreads();
    }
}

// ---------------- fused FC+XPROJ: persistent cluster-of-4 ----------------
// 37 clusters x 4 CTAs, 256 thr. Per 64-row tile: each CTA computes fc for its 16
// rows, DSMEM-broadcasts feats to all peers, then applies its 128-col xproj panel
// to all 64 rows. g_feats intermediate eliminated.
__global__ void __launch_bounds__(256, 1) __cluster_dims__(4, 1, 1)
ffx_kernel(const float* __restrict__ fc1w, const float* __restrict__ fc1b,
           const float* __restrict__ g1, const float* __restrict__ be1,
           const float* __restrict__ m1, const float* __restrict__ v1,
           const float* __restrict__ fc2w, const float* __restrict__ fc2b,
           const float* __restrict__ g2, const float* __restrict__ be2,
           const float* __restrict__ m2, const float* __restrict__ v2,
           const float* __restrict__ wih, const float* __restrict__ eb)
{
    extern __shared__ float sm[];
    float* w1s = sm;                        // 128 x WPAD
    float* w2s = w1s + 128 * WPAD;          // 64 x WPAD
    float* Bs  = w2s + 64 * WPAD;           // 128 x BPAD (xproj panel)
    float* xs  = Bs + 128 * BPAD;           // 16 x 128
    float* ms  = xs + 16 * 128;             // 16 x 128
    float* fs  = ms + 16 * 128;             // 64 x 64 (cluster-shared feats)

    int tid = threadIdx.x;
    unsigned rank = blockIdx.x & 3;
    int cl = blockIdx.x >> 2;   // 0..36
    int j0 = rank * 128;

    for (int i = tid; i < 128 * 128; i += 256) {
        int row = i >> 7, k = i & 127;
        w1s[row * WPAD + k] = fc1w[i];
    }
    for (int i = tid; i < 64 * 128; i += 256) {
        int row = i >> 7, k = i & 127;
        w2s[row * WPAD + k] = fc2w[i];
    }
    for (int i = tid; i < 128 * 64; i += 256) {
        int j = i >> 6, k = i & 63;
        Bs[j * BPAD + k] = wih[(long)(j0 + j) * 64 + k];
    }

    int tj = tid & 31, tr8 = tid >> 5;   // fc indexing
    float s1[4], bb1[4], s2[2], bb2[2];
#pragma unroll
    for (int a = 0; a < 4; a++) {
        int j = tj + 32 * a;
        s1[a] = g1[j] * rsqrtf(v1[j] + 1e-5f);
        bb1[a] = (fc1b[j] - m1[j]) * s1[a] + be1[j];
    }
#pragma unroll
    for (int a = 0; a < 2; a++) {
        int j = tj + 32 * a;
        s2[a] = g2[j] * rsqrtf(v2[j] + 1e-5f);
        bb2[a] = (fc2b[j] - m2[j]) * s2[a] + be2[j];
    }

    int tx = tid & 15, ty = tid >> 4;    // xproj indexing
    float ebv[8];
#pragma unroll
    for (int j = 0; j < 8; j++) ebv[j] = eb[j0 + tx + 16 * j];

    unsigned fs_local = smem_u32(fs);
    unsigned rbf[4];
#pragma unroll
    for (int r = 0; r < 4; r++)
        asm("mapa.shared::cluster.u32 %0, %1, %2;" : "=r"(rbf[r]) : "r"(fs_local), "r"(r));

    __syncthreads();
    asm volatile("barrier.cluster.arrive.aligned;" ::: "memory");
    asm volatile("barrier.cluster.wait.aligned;" ::: "memory");

    for (int t = cl; t < 512; t += 37) {
        long r0 = (long)t * 64;
        long rr = r0 + rank * 16;
        for (int i = tid; i < 16 * 128; i += 256) xs[i] = g_cnn[rr * 128 + i];
        __syncthreads();

        // fc1 -> ms (16 rows x 128)
        {
            unsigned long long acc2[4][2];
#pragma unroll
            for (int a = 0; a < 4; a++)
#pragma unroll
                for (int b = 0; b < 2; b++) acc2[a][b] = 0ull;
            for (int kk = 0; kk < 32; kk++) {
                ulonglong2 w2v[4], h2v[2];
#pragma unroll
                for (int a = 0; a < 4; a++)
                    w2v[a] = *reinterpret_cast<const ulonglong2*>(&w1s[(tj + 32 * a) * WPAD + (kk << 2)]);
#pragma unroll
                for (int b = 0; b < 2; b++)
                    h2v[b] = *reinterpret_cast<const ulonglong2*>(&xs[(tr8 + 8 * b) * 128 + (kk << 2)]);
#pragma unroll
                for (int a = 0; a < 4; a++)
#pragma unroll
                    for (int b = 0; b < 2; b++) {
                        fma2(acc2[a][b], w2v[a].x, h2v[b].x);
                        fma2(acc2[a][b], w2v[a].y, h2v[b].y);
                    }
            }
#pragma unroll
            for (int a = 0; a < 4; a++) {
                int j = tj + 32 * a;
#pragma unroll
                for (int b = 0; b < 2; b++)
                    ms[(tr8 + 8 * b) * 128 + j] = fmaxf(f2sum(acc2[a][b]) * s1[a] + bb1[a], 0.f);
            }
        }
        __syncthreads();

        // fc2 -> feats, DSMEM-broadcast into all peers' fs at rows rank*16..+16
        {
            unsigned long long acc2[2][2];
#pragma unroll
            for (int a = 0; a < 2; a++)
#pragma unroll
                for (int b = 0; b < 2; b++) acc2[a][b] = 0ull;
            for (int kk = 0; kk < 32; kk++) {
                ulonglong2 w2v[2], h2v[2];
#pragma unroll
                for (int a = 0; a < 2; a++)
                    w2v[a] = *reinterpret_cast<const ulonglong2*>(&w2s[(tj + 32 * a) * WPAD + (kk << 2)]);
#pragma unroll
                for (int b = 0; b < 2; b++)
                    h2v[b] = *reinterpret_cast<const ulonglong2*>(&ms[(tr8 + 8 * b) * 128 + (kk << 2)]);
#pragma unroll
                for (int a = 0; a < 2; a++)
#pragma unroll
                    for (int b = 0; b < 2; b++) {
                        fma2(acc2[a][b], w2v[a].x, h2v[b].x);
                        fma2(acc2[a][b], w2v[a].y, h2v[b].y);
                    }
            }
#pragma unroll
            for (int a = 0; a < 2; a++) {
                int col = tj + 32 * a;
#pragma unroll
                for (int b = 0; b < 2; b++) {
                    float f = fmaxf(f2sum(acc2[a][b]) * s2[a] + bb2[a], 0.f);
                    unsigned off = (unsigned)(((rank * 16 + tr8 + 8 * b) * 64 + col) * 4);
#pragma unroll
                    for (int r = 0; r < 4; r++)
                        asm volatile("st.shared::cluster.f32 [%0], %1;"
                                     :: "r"(rbf[r] + off), "f"(f) : "memory");
                }
            }
        }
        asm volatile("barrier.cluster.arrive.aligned;" ::: "memory");
        asm volatile("barrier.cluster.wait.aligned;" ::: "memory");

        // xproj: this CTA's 128-col panel applied to all 64 rows in fs
        {
            unsigned long long acc2[4][8];
#pragma unroll
            for (int i = 0; i < 4; i++)
#pragma unroll
                for (int j = 0; j < 8; j++) acc2[i][j] = 0ull;
            for (int kk = 0; kk < 16; kk++) {
                ulonglong2 a2[4], b2[8];
#pragma unroll
                for (int i = 0; i < 4; i++)
                    a2[i] = *reinterpret_cast<const ulonglong2*>(&fs[(ty * 4 + i) * 64 + (kk << 2)]);
#pragma unroll
                for (int j = 0; j < 8; j++)
                    b2[j] = *reinterpret_cast<const ulonglong2*>(&Bs[(tx + 16 * j) * BPAD + (kk << 2)]);
#pragma unroll
                for (int i = 0; i < 4; i++)
#pragma unroll
                    for (int j = 0; j < 8; j++) {
                        fma2(acc2[i][j], a2[i].x, b2[j].x);
                        fma2(acc2[i][j], a2[i].y, b2[j].y);
                    }
            }
#pragma unroll
            for (int i = 0; i < 4; i++) {
                long row = (r0 + ty * 4 + i) * 512 + j0;
#pragma unroll
                for (int j = 0; j < 8; j++)
                    g_xg[row + tx + 16 * j] = f2sum(acc2[i][j]) + ebv[j];
            }
        }
        // protect fs (peers write it next tile) and xs/ms reuse
        asm volatile("barrier.cluster.arrive.aligned;" ::: "memory");
        asm volatile("barrier.cluster.wait.aligned;" ::: "memory");
    }
}

// ---------------- persistent LSTM: clusters of 4, DSMEM h, b=8 + k-split-2 ----------
// 8 warps (256 thr): warps 0-3 (kh=0) k-low + gate math, warps 4-7 (kh=1) k-high.
// Weight LDS wavefronts: 2048/step (was 4096) -> fma-pipe becomes the binding floor.
#define SR2 33
__global__ void __launch_bounds__(256, 1) __cluster_dims__(4, 1, 1)
lstm_persistent(const float* __restrict__ encw, const float* __restrict__ dwi,
                const float* __restrict__ dwh, const float* __restrict__ decb)
{
    extern __shared__ float sm[];
    float* wse = sm;                     // 128 x WPAD encoder slice
    float* wsd = sm + 128 * WPAD;        // 128 x WPAD decoder slice (ih+hh)
    float* hs  = sm + 2 * 128 * WPAD;    // 2 buffers x 32 x 128
    float* sred = hs + 2 * 32 * 128;     // 128 x SR2 reduce pad

    int tid = threadIdx.x;
    unsigned rank = blockIdx.x & 3;
    int b0 = (blockIdx.x >> 2) * 32;
    int u0 = rank * 32;

    for (int i = tid; i < 128 * 128; i += 256) {
        int row = i >> 7, k = i & 127;
        int grow = ((row >> 5) * 128) + u0 + (row & 31);
        wse[row * WPAD + k] = encw[grow * 128 + k];
        wsd[row * WPAD + k] = dwi[grow * 128 + k] + dwh[grow * 128 + k];
    }
    for (int i = tid; i < 32 * 128; i += 256) hs[i] = 0.f;

    unsigned hs_local = smem_u32(hs);
    unsigned rb[4];
#pragma unroll
    for (int r = 0; r < 4; r++)
        asm("mapa.shared::cluster.u32 %0, %1, %2;" : "=r"(rb[r]) : "r"(hs_local), "r"(r));

    __syncthreads();
    asm volatile("barrier.cluster.arrive.aligned;" ::: "memory");
    asm volatile("barrier.cluster.wait.aligned;" ::: "memory");

    int tj = tid & 31;
    int w  = tid >> 5;          // 0..7
    int kh = w >> 2;            // 0 = k-low (+ gate math), 1 = k-high
    int tr = w & 3;             // batch rows tr + 4*b, b<8
    int u = u0 + tj;
    float db[4];
#pragma unroll
    for (int a = 0; a < 4; a++) db[a] = decb[a * 128 + u];

    float c[8] = {0.f, 0.f, 0.f, 0.f, 0.f, 0.f, 0.f, 0.f};

    float xn[8][4];
    if (kh == 0) {
#pragma unroll
        for (int b = 0; b < 8; b++) {
            const float* xr = g_xg + ((long)(b0 + tr + 4 * b) * 32 + 0) * 512;
#pragma unroll
            for (int a = 0; a < 4; a++) xn[b][a] = xr[a * 128 + u];
        }
    }

    int kbase = kh * 16;
    int pread = 0;
    for (int step = 0; step < 42; step++) {
        const float* ws = (step < 32) ? wse : wsd;
        const float* hsr = hs + pread * (32 * 128);

        unsigned long long acc2[4][8];
#pragma unroll
        for (int a = 0; a < 4; a++)
#pragma unroll
            for (int b = 0; b < 8; b++) acc2[a][b] = 0ull;

        for (int kk = kbase; kk < kbase + 16; kk++) {
            ulonglong2 w2v[4], h2v[8];
#pragma unroll
            for (int a = 0; a < 4; a++)
                w2v[a] = *reinterpret_cast<const ulonglong2*>(&ws[(a * 32 + tj) * WPAD + (kk << 2)]);
#pragma unroll
            for (int b = 0; b < 8; b++)
                h2v[b] = *reinterpret_cast<const ulonglong2*>(&hsr[(tr + 4 * b) * 128 + (kk << 2)]);
#pragma unroll
            for (int a = 0; a < 4; a++)
#pragma unroll
                for (int b = 0; b < 8; b++) {
                    fma2(acc2[a][b], w2v[a].x, h2v[b].x);
                    fma2(acc2[a][b], w2v[a].y, h2v[b].y);
                }
        }

        if (kh == 1) {
            float* dst = sred + (tid - 128) * SR2;
#pragma unroll
            for (int a = 0; a < 4; a++)
#pragma unroll
                for (int b = 0; b < 8; b++) dst[a * 8 + b] = f2sum(acc2[a][b]);
        }
        __syncthreads();

        if (kh == 0) {
            const float* src = sred + tid * SR2;
            unsigned woff = (unsigned)((1 - pread) * (32 * 128 * 4));
#pragma unroll
            for (int b = 0; b < 8; b++) {
                int rloc = tr + 4 * b;
                float gi = f2sum(acc2[0][b]) + src[0 * 8 + b] + xn[b][0];
                float gf = f2sum(acc2[1][b]) + src[1 * 8 + b] + xn[b][1];
                float gg = f2sum(acc2[2][b]) + src[2 * 8 + b] + xn[b][2];
                float go = f2sum(acc2[3][b]) + src[3 * 8 + b] + xn[b][3];
                float si = 1.f / (1.f + __expf(-gi));
                float sf = 1.f / (1.f + __expf(-gf));
                float so = 1.f / (1.f + __expf(-go));
                float tg = tanhf(gg);
                float cn = sf * c[b] + si * tg;
                c[b] = cn;
                float hn = so * tanhf(cn);
                if (step < 41) {
                    unsigned eoff = woff + (unsigned)(rloc * 128 + u) * 4u;
#pragma unroll
                    for (int r = 0; r < 4; r++)
                        asm volatile("st.shared::cluster.f32 [%0], %1;"
                                     :: "r"(rb[r] + eoff), "f"(hn) : "memory");
                }
                if (step >= 32) g_hdec[step - 32][(b0 + rloc) * 128 + u] = hn;
            }
        }

        if (step < 41) {
            asm volatile("barrier.cluster.arrive.aligned;" ::: "memory");
            if (kh == 0) {
                if (step + 1 < 32) {
#pragma unroll
                    for (int b = 0; b < 8; b++) {
                        const float* xr = g_xg + ((long)(b0 + tr + 4 * b) * 32 + (step + 1)) * 512;
#pragma unroll
                        for (int a = 0; a < 4; a++) xn[b][a] = xr[a * 128 + u];
                    }
                } else {
#pragma unroll
                    for (int b = 0; b < 8; b++)
#pragma unroll
                        for (int a = 0; a < 4; a++) xn[b][a] = db[a];
                }
            }
            asm volatile("barrier.cluster.wait.aligned;" ::: "memory");
            pread ^= 1;
        }
    }

    asm volatile("barrier.cluster.arrive.aligned;" ::: "memory");
    asm volatile("barrier.cluster.wait.aligned;" ::: "memory");
}

// ---------------- output head ----------------
__global__ void head_kernel(const float* __restrict__ ow, const float* __restrict__ ob,
                            float* __restrict__ out)
{
    __shared__ float hsm[64 * 129];
    __shared__ float wsm[12 * 129];
    __shared__ float bsm[12];
    int tid = threadIdx.x;
    int s = blockIdx.y, b0 = blockIdx.x * 64;
    for (int i = tid; i < 64 * 128; i += 256) {
        int r = i >> 7, k = i & 127;
        hsm[r * 129 + k] = g_hdec[s][(b0 + r) * 128 + k];
    }
    for (int i = tid; i < 12 * 128; i += 256) {
        int r = i / 128, k = i % 128;
        wsm[r * 129 + k] = ow[i];
    }
    if (tid < 12) bsm[tid] = ob[tid];
    __syncthreads();
    for (int it = tid; it < 64 * 12; it += 256) {
        int b = it / 12, v = it % 12;
        float acc = bsm[v];
        for (int k = 0; k < 128; k++) acc += hsm[b * 129 + k] * wsm[v * 129 + k];
        out[(long)(b0 + b) * 120 + s * 12 + v] = acc;
    }
}

// ---------------- launcher ----------------
extern "C" void kernel_launch(void* const* d_in, const int* in_sizes, int n_in,
                              void* d_out, int out_size)
{
    const float* obs    = (const float*)d_in[0];
    const float* c1w    = (const float*)d_in[1];
    const float* c1b    = (const float*)d_in[2];
    const float* c2w    = (const float*)d_in[3];
    const float* c2b    = (const float*)d_in[4];
    const float* fc1w   = (const float*)d_in[5];
    const float* fc1b   = (const float*)d_in[6];
    const float* bn1g   = (const float*)d_in[7];
    const float* bn1b   = (const float*)d_in[8];
    const float* bn1m   = (const float*)d_in[9];
    const float* bn1v   = (const float*)d_in[10];
    const float* fc2w   = (const float*)d_in[11];
    const float* fc2b   = (const float*)d_in[12];
    const float* bn2g   = (const float*)d_in[13];
    const float* bn2b   = (const float*)d_in[14];
    const float* bn2m   = (const float*)d_in[15];
    const float* bn2v   = (const float*)d_in[16];
    const float* encwih = (const float*)d_in[17];
    const float* encwhh = (const float*)d_in[18];
    const float* encb   = (const float*)d_in[19];
    const float* decwih = (const float*)d_in[20];
    const float* decwhh = (const float*)d_in[21];
    const float* decb   = (const float*)d_in[22];
    const float* outw   = (const float*)d_in[23];
    const float* outb   = (const float*)d_in[24];
    float* out = (float*)d_out;

    const int ffx_smem  = (128 * WPAD + 64 * WPAD + 128 * BPAD + 16 * 128 * 2 + 64 * 64) * 4;
    const int lstm_smem = (2 * 128 * WPAD + 2 * 32 * 128 + 128 * SR2) * 4;
    cudaFuncSetAttribute(ffx_kernel, cudaFuncAttributeMaxDynamicSharedMemorySize, ffx_smem);
    cudaFuncSetAttribute(lstm_persistent, cudaFuncAttributeMaxDynamicSharedMemorySize, lstm_smem);

    cnn_kernel<<<CNN_GRID, 128>>>(obs, c1w, c1b, c2w, c2b);
    ffx_kernel<<<148, 256, ffx_smem>>>(fc1w, fc1b, bn1g, bn1b, bn1m, bn1v,
                                       fc2w, fc2b, bn2g, bn2b, bn2m, bn2v,
                                       encwih, encb);
    lstm_persistent<<<128, 256, lstm_smem>>>(encwhh, decwih, decwhh, decb);

    dim3 hgrid(16, 10);
    head_kernel<<<hgrid, 256>>>(outw, outb, out);
}

// round 12
// speedup vs baseline: 1.2998x; 1.2998x over previous
#include <cuda_runtime.h>
#include <math.h>

// ---------------- scratch (static device globals; no allocation) ----------------
__device__ float g_cnn[32768 * 128];     // CNN output per frame
__device__ float g_feats[32768 * 64];    // after FC+BN stack
__device__ float g_xg[32768 * 512];      // precomputed x @ enc_w_ih^T + enc_b
__device__ float g_hdec[10][1024 * 128]; // decoder h history for output head

#define WPAD 132   // weight row pad: 132 % 32 == 4 (conflict-free LDS.128 phases)

__device__ __forceinline__ void fma2(unsigned long long& d,
                                     unsigned long long a, unsigned long long b) {
    asm("fma.rn.f32x2 %0, %1, %2, %0;" : "+l"(d) : "l"(a), "l"(b));
}
__device__ __forceinline__ unsigned long long pack2(float v) {
    unsigned long long r;
    asm("mov.b64 %0, {%1, %1};" : "=l"(r) : "f"(v));
    return r;
}
__device__ __forceinline__ unsigned long long packab(float a, float b) {
    unsigned long long r;
    asm("mov.b64 %0, {%1, %2};" : "=l"(r) : "f"(a), "f"(b));
    return r;
}
__device__ __forceinline__ float ulo(unsigned long long v) {
    return __uint_as_float((unsigned)(v & 0xffffffffull));
}
__device__ __forceinline__ float uhi(unsigned long long v) {
    return __uint_as_float((unsigned)(v >> 32));
}
__device__ __forceinline__ float f2sum(unsigned long long v) { return ulo(v) + uhi(v); }
__device__ __forceinline__ unsigned smem_u32(const void* p) {
    unsigned a;
    asm("{ .reg .u64 t; cvta.to.shared.u64 t, %1; cvt.u32.u64 %0, t; }" : "=r"(a) : "l"(p));
    return a;
}

// ---------------- CNN: persistent, frame-pair packed f32x2 ----------------
#define FPB 4
#define IRS 50
#define CNN_GRID 592
__global__ void __launch_bounds__(128) cnn_kernel(
    const float* __restrict__ obs,
    const float* __restrict__ w1, const float* __restrict__ b1,
    const float* __restrict__ w2, const float* __restrict__ b2)
{
    __shared__ float s_ini[4 * 12 * IRS];
    __shared__ float s_p1i[16 * 7 * 2 * 16];
    __shared__ float s_w1[576];
    __shared__ float s_b1[16];
    __shared__ float s_w2t[144 * 33];
    __shared__ float s_b2[32];

    int tid = threadIdx.x; // 128
    for (int i = tid; i < 4 * 12 * IRS; i += 128) s_ini[i] = 0.f;
    for (int i = tid; i < 16 * 7 * 2 * 16; i += 128) s_p1i[i] = 0.f;
    for (int i = tid; i < 576; i += 128) s_w1[i] = w1[i];
    if (tid < 16) s_b1[tid] = b1[tid];
    for (int i = tid; i < 4608; i += 128) {
        int oc = i / 144, r = i % 144;
        s_w2t[r * 33 + oc] = w2[i];
    }
    if (tid < 32) s_b2[tid] = b2[tid];
    __syncthreads();

    for (long f0 = (long)blockIdx.x * FPB; f0 < 32768; f0 += (long)gridDim.x * FPB) {
        for (int i = tid; i < FPB * 400; i += 128) {
            int f = i / 400, rem = i % 400;
            int ic = rem / 100, p = rem % 100, y = p / 10, x = p % 10;
            s_ini[(ic * 12 + y + 1) * IRS + (x + 1) * 4 + f] = obs[f0 * 400 + i];
        }
        __syncthreads();

        if (tid < 100) {
            int fp = tid / 50, rem = tid % 50, ocg = rem / 25, pos = rem % 25;
            int py = pos / 5, px = pos % 5;
            unsigned long long acc2[8][4];
#pragma unroll
            for (int o = 0; o < 8; o++) {
                unsigned long long bp = pack2(s_b1[ocg * 8 + o]);
#pragma unroll
                for (int p = 0; p < 4; p++) acc2[o][p] = bp;
            }
#pragma unroll
            for (int ic = 0; ic < 4; ic++) {
                unsigned long long patch2[4][4];
#pragma unroll
                for (int r = 0; r < 4; r++)
#pragma unroll
                    for (int cc = 0; cc < 4; cc++)
                        patch2[r][cc] = *(const unsigned long long*)
                            &s_ini[(ic * 12 + 2 * py + r) * IRS + (2 * px + cc) * 4 + fp * 2];
#pragma unroll
                for (int o = 0; o < 8; o++) {
                    int oc = ocg * 8 + o;
#pragma unroll
                    for (int ky = 0; ky < 3; ky++)
#pragma unroll
                        for (int kx = 0; kx < 3; kx++) {
                            unsigned long long wp = pack2(s_w1[(oc * 4 + ic) * 9 + ky * 3 + kx]);
                            fma2(acc2[o][0], patch2[ky][kx], wp);
                            fma2(acc2[o][1], patch2[ky][kx + 1], wp);
                            fma2(acc2[o][2], patch2[ky + 1][kx], wp);
                            fma2(acc2[o][3], patch2[ky + 1][kx + 1], wp);
                        }
                }
            }
#pragma unroll
            for (int o = 0; o < 8; o++) {
                int oc = ocg * 8 + o;
                float mlo = fmaxf(fmaxf(ulo(acc2[o][0]), ulo(acc2[o][1])),
                                  fmaxf(ulo(acc2[o][2]), ulo(acc2[o][3])));
                float mhi = fmaxf(fmaxf(uhi(acc2[o][0]), uhi(acc2[o][1])),
                                  fmaxf(uhi(acc2[o][2]), uhi(acc2[o][3])));
                unsigned long long pk = packab(fmaxf(mlo, 0.f), fmaxf(mhi, 0.f));
                int idx = ((oc * 7 + py + 1) * 2 + fp) * 16 + (px + 1) * 2;
                *(unsigned long long*)&s_p1i[idx] = pk;
            }
        }
        __syncthreads();

        {
            int half = tid >> 6, fp = (tid >> 5) & 1, oc = tid & 31;
            unsigned long long acc2[2][4];
            unsigned long long bp = pack2(s_b2[oc]);
#pragma unroll
            for (int yl = 0; yl < 2; yl++)
#pragma unroll
                for (int x = 0; x < 4; x++) acc2[yl][x] = bp;

            for (int ic = 0; ic < 16; ic++) {
                unsigned long long in2[4][6];
#pragma unroll
                for (int rl = 0; rl < 4; rl++)
#pragma unroll
                    for (int cp = 0; cp < 3; cp++) {
                        ulonglong2 v = *(const ulonglong2*)
                            &s_p1i[((ic * 7 + 2 * half + rl) * 2 + fp) * 16 + cp * 4];
                        in2[rl][2 * cp] = v.x;
                        in2[rl][2 * cp + 1] = v.y;
                    }
#pragma unroll
                for (int ky = 0; ky < 3; ky++)
#pragma unroll
                    for (int kx = 0; kx < 3; kx++) {
                        unsigned long long wp = pack2(s_w2t[(ic * 9 + ky * 3 + kx) * 33 + oc]);
#pragma unroll
                        for (int yl = 0; yl < 2; yl++)
#pragma unroll
                            for (int x = 0; x < 4; x++)
                                fma2(acc2[yl][x], in2[yl + ky][x + kx], wp);
                    }
            }
#pragma unroll
            for (int px = 0; px < 2; px++) {
                float mlo = fmaxf(fmaxf(ulo(acc2[0][2 * px]), ulo(acc2[0][2 * px + 1])),
                                  fmaxf(ulo(acc2[1][2 * px]), ulo(acc2[1][2 * px + 1])));
                float mhi = fmaxf(fmaxf(uhi(acc2[0][2 * px]), uhi(acc2[0][2 * px + 1])),
                                  fmaxf(uhi(acc2[1][2 * px]), uhi(acc2[1][2 * px + 1])));
                long fr = f0 + fp * 2;
                g_cnn[fr * 128 + oc * 4 + half * 2 + px] = fmaxf(mlo, 0.f);
                g_cnn[(fr + 1) * 128 + oc * 4 + half * 2 + px] = fmaxf(mhi, 0.f);
            }
        }
        __syncthreads();
    }
}

// ---------------- FC stack: persistent; fc1+bn1+relu -> fc2+bn2+relu ----------------
#define FC_GRID 148
__global__ void __launch_bounds__(256) fc_kernel(
    const float* __restrict__ fc1w, const float* __restrict__ fc1b,
    const float* __restrict__ g1, const float* __restrict__ be1,
    const float* __restrict__ m1, const float* __restrict__ v1,
    const float* __restrict__ fc2w, const float* __restrict__ fc2b,
    const float* __restrict__ g2, const float* __restrict__ be2,
    const float* __restrict__ m2, const float* __restrict__ v2)
{
    extern __shared__ float sm[];
    float* w1s = sm;                   // 128 rows x WPAD
    float* w2s = w1s + 128 * WPAD;     // 64 rows x WPAD
    float* xs  = w2s + 64 * WPAD;      // 64 x 128 plain
    float* ms  = xs + 64 * 128;        // 64 x 128 plain

    int tid = threadIdx.x;
    for (int i = tid; i < 128 * 128; i += 256) {
        int row = i >> 7, k = i & 127;
        w1s[row * WPAD + k] = fc1w[i];
    }
    for (int i = tid; i < 64 * 128; i += 256) {
        int row = i >> 7, k = i & 127;
        w2s[row * WPAD + k] = fc2w[i];
    }
    int tj = tid & 31, tr = tid >> 5;
    float s1[4], bb1[4], s2[2], bb2[2];
#pragma unroll
    for (int a = 0; a < 4; a++) {
        int j = tj + 32 * a;
        s1[a] = g1[j] * rsqrtf(v1[j] + 1e-5f);
        bb1[a] = (fc1b[j] - m1[j]) * s1[a] + be1[j];
    }
#pragma unroll
    for (int a = 0; a < 2; a++) {
        int j = tj + 32 * a;
        s2[a] = g2[j] * rsqrtf(v2[j] + 1e-5f);
        bb2[a] = (fc2b[j] - m2[j]) * s2[a] + be2[j];
    }

    for (long t = blockIdx.x; t < 512; t += gridDim.x) {
        long r0 = t * 64;
        for (int i = tid; i < 64 * 128; i += 256) xs[i] = g_cnn[r0 * 128 + i];
        __syncthreads();
        {
            unsigned long long acc2[4][8];
#pragma unroll
            for (int a = 0; a < 4; a++)
#pragma unroll
                for (int b = 0; b < 8; b++) acc2[a][b] = 0ull;
            for (int kk = 0; kk < 32; kk++) {
                ulonglong2 w2v[4], h2v[8];
#pragma unroll
                for (int a = 0; a < 4; a++)
                    w2v[a] = *reinterpret_cast<const ulonglong2*>(&w1s[(tj + 32 * a) * WPAD + (kk << 2)]);
#pragma unroll
                for (int b = 0; b < 8; b++)
                    h2v[b] = *reinterpret_cast<const ulonglong2*>(&xs[(tr * 8 + b) * 128 + (kk << 2)]);
#pragma unroll
                for (int a = 0; a < 4; a++)
#pragma unroll
                    for (int b = 0; b < 8; b++) {
                        fma2(acc2[a][b], w2v[a].x, h2v[b].x);
                        fma2(acc2[a][b], w2v[a].y, h2v[b].y);
                    }
            }
#pragma unroll
            for (int a = 0; a < 4; a++) {
                int j = tj + 32 * a;
#pragma unroll
                for (int b = 0; b < 8; b++)
                    ms[(tr * 8 + b) * 128 + j] = fmaxf(f2sum(acc2[a][b]) * s1[a] + bb1[a], 0.f);
            }
        }
        __syncthreads();
        {
            unsigned long long acc2[2][8];
#pragma unroll
            for (int a = 0; a < 2; a++)
#pragma unroll
                for (int b = 0; b < 8; b++) acc2[a][b] = 0ull;
            for (int kk = 0; kk < 32; kk++) {
                ulonglong2 w2v[2], h2v[8];
#pragma unroll
                for (int a = 0; a < 2; a++)
                    w2v[a] = *reinterpret_cast<const ulonglong2*>(&w2s[(tj + 32 * a) * WPAD + (kk << 2)]);
#pragma unroll
                for (int b = 0; b < 8; b++)
                    h2v[b] = *reinterpret_cast<const ulonglong2*>(&ms[(tr * 8 + b) * 128 + (kk << 2)]);
#pragma unroll
                for (int a = 0; a < 2; a++)
#pragma unroll
                    for (int b = 0; b < 8; b++) {
                        fma2(acc2[a][b], w2v[a].x, h2v[b].x);
                        fma2(acc2[a][b], w2v[a].y, h2v[b].y);
                    }
            }
#pragma unroll
            for (int a = 0; a < 2; a++) {
                int j = tj + 32 * a;
#pragma unroll
                for (int b = 0; b < 8; b++)
                    g_feats[(r0 + tr * 8 + b) * 64 + j] = fmaxf(f2sum(acc2[a][b]) * s2[a] + bb2[a], 0.f);
            }
        }
        __syncthreads();
    }
}

// ---------------- encoder x-projection GEMM: persistent, j-panel staged once --------
#define BPAD 68   // 68 % 32 == 4
#define XP_GROUPS 111
__global__ void __launch_bounds__(512) xproj_kernel(const float* __restrict__ wih,
                                                    const float* __restrict__ eb)
{
    extern __shared__ float sm[];
    float* As = sm;               // [128][64] plain (m-major)
    float* Bs = sm + 128 * 64;    // [128][BPAD] (j-major, padded)

    int tid = threadIdx.x;
    int j0 = (blockIdx.x & 3) * 128;
    int grp = blockIdx.x >> 2;    // 0..XP_GROUPS-1

    for (int i = tid; i < 128 * 64; i += 512) {
        int j = i >> 6, k = i & 63;
        Bs[j * BPAD + k] = wih[(long)(j0 + j) * 64 + k];
    }

    int tx = tid & 15, ty = tid >> 4; // ty 0..31
    int m0 = ty * 4;
    float ebv[8];
#pragma unroll
    for (int j = 0; j < 8; j++) ebv[j] = eb[j0 + tx + 16 * j];

    for (int t = grp; t < 256; t += XP_GROUPS) {
        long r0 = (long)t * 128;
        for (int i = tid; i < 128 * 64; i += 512) As[i] = g_feats[r0 * 64 + i];
        __syncthreads();

        unsigned long long acc2[4][8];
#pragma unroll
        for (int i = 0; i < 4; i++)
#pragma unroll
            for (int j = 0; j < 8; j++) acc2[i][j] = 0ull;

        for (int kk = 0; kk < 16; kk++) {
            ulonglong2 a2[4], b2[8];
#pragma unroll
            for (int i = 0; i < 4; i++)
                a2[i] = *reinterpret_cast<const ulonglong2*>(&As[(m0 + i) * 64 + (kk << 2)]);
#pragma unroll
            for (int j = 0; j < 8; j++)
                b2[j] = *reinterpret_cast<const ulonglong2*>(&Bs[(tx + 16 * j) * BPAD + (kk << 2)]);
#pragma unroll
            for (int i = 0; i < 4; i++)
#pragma unroll
                for (int j = 0; j < 8; j++) {
                    fma2(acc2[i][j], a2[i].x, b2[j].x);
                    fma2(acc2[i][j], a2[i].y, b2[j].y);
                }
        }

#pragma unroll
        for (int i = 0; i < 4; i++) {
            long row = (r0 + m0 + i) * 512 + j0;
#pragma unroll
            for (int j = 0; j < 8; j++)
                g_xg[row + tx + 16 * j] = f2sum(acc2[i][j]) + ebv[j];
        }
        __syncthreads();
    }
}

// ---------------- persistent LSTM: clusters of 4, DSMEM h, k-split 16 warps ----------
#define SRSTRIDE 17
__global__ void __launch_bounds__(512, 1) __cluster_dims__(4, 1, 1)
lstm_persistent(const float* __restrict__ encw, const float* __restrict__ dwi,
                const float* __restrict__ dwh, const float* __restrict__ decb)
{
    extern __shared__ float sm[];
    float* wse = sm;                     // 128 rows x WPAD encoder slice
    float* wsd = sm + 128 * WPAD;        // 128 rows x WPAD decoder slice (ih+hh)
    float* hs  = sm + 2 * 128 * WPAD;    // 2 buffers x 32 x 128
    float* sred = hs + 2 * 32 * 128;     // 256 x SRSTRIDE reduce pad

    int tid = threadIdx.x;
    unsigned rank = blockIdx.x & 3;
    int b0 = (blockIdx.x >> 2) * 32;
    int u0 = rank * 32;

    for (int i = tid; i < 128 * 128; i += 512) {
        int row = i >> 7, k = i & 127;
        int grow = ((row >> 5) * 128) + u0 + (row & 31);
        wse[row * WPAD + k] = encw[grow * 128 + k];
        wsd[row * WPAD + k] = dwi[grow * 128 + k] + dwh[grow * 128 + k];
    }
    for (int i = tid; i < 32 * 128; i += 512) hs[i] = 0.f;

    unsigned hs_local = smem_u32(hs);
    unsigned rb[4];
#pragma unroll
    for (int r = 0; r < 4; r++)
        asm("mapa.shared::cluster.u32 %0, %1, %2;" : "=r"(rb[r]) : "r"(hs_local), "r"(r));

    __syncthreads();
    asm volatile("barrier.cluster.arrive.aligned;" ::: "memory");
    asm volatile("barrier.cluster.wait.aligned;" ::: "memory");

    int tj = tid & 31;
    int w  = tid >> 5;          // 0..15
    int kh = w >> 3;            // 0 = k-low half, 1 = k-high half
    int tr = w & 7;             // batch rows tr + 8*b
    int u = u0 + tj;
    float db[4];
#pragma unroll
    for (int a = 0; a < 4; a++) db[a] = decb[a * 128 + u];

    float c[4] = {0.f, 0.f, 0.f, 0.f};

    float xn[4][4];
    if (kh == 0) {
#pragma unroll
        for (int b = 0; b < 4; b++) {
            const float* xr = g_xg + ((long)(b0 + tr + 8 * b) * 32 + 0) * 512;
#pragma unroll
            for (int a = 0; a < 4; a++) xn[b][a] = xr[a * 128 + u];
        }
    }

    int kbase = kh * 16;   // kk-chunk offset (units of 4 floats)
    int pread = 0;
    for (int step = 0; step < 42; step++) {
        const float* ws = (step < 32) ? wse : wsd;
        const float* hsr = hs + pread * (32 * 128);

        unsigned long long acc2[4][4];
#pragma unroll
        for (int a = 0; a < 4; a++)
#pragma unroll
            for (int b = 0; b < 4; b++) acc2[a][b] = 0ull;

        for (int kk = kbase; kk < kbase + 16; kk++) {
            ulonglong2 w2v[4], h2v[4];
#pragma unroll
            for (int a = 0; a < 4; a++)
                w2v[a] = *reinterpret_cast<const ulonglong2*>(&ws[(a * 32 + tj) * WPAD + (kk << 2)]);
#pragma unroll
            for (int b = 0; b < 4; b++)
                h2v[b] = *reinterpret_cast<const ulonglong2*>(&hsr[(tr + 8 * b) * 128 + (kk << 2)]);
#pragma unroll
            for (int a = 0; a < 4; a++)
#pragma unroll
                for (int b = 0; b < 4; b++) {
                    fma2(acc2[a][b], w2v[a].x, h2v[b].x);
                    fma2(acc2[a][b], w2v[a].y, h2v[b].y);
                }
        }

        // k-high warps publish partials; k-low warps reduce + gate math
        if (kh == 1) {
            float* dst = sred + (tid - 256) * SRSTRIDE;
#pragma unroll
            for (int a = 0; a < 4; a++)
#pragma unroll
                for (int b = 0; b < 4; b++) dst[a * 4 + b] = f2sum(acc2[a][b]);
        }
        __syncthreads();

        if (kh == 0) {
            const float* src = sred + tid * SRSTRIDE;
            unsigned woff = (unsigned)((1 - pread) * (32 * 128 * 4));
#pragma unroll
            for (int b = 0; b < 4; b++) {
                int rloc = tr + 8 * b;
                float gi = f2sum(acc2[0][b]) + src[0 * 4 + b] + xn[b][0];
                float gf = f2sum(acc2[1][b]) + src[1 * 4 + b] + xn[b][1];
                float gg = f2sum(acc2[2][b]) + src[2 * 4 + b] + xn[b][2];
                float go = f2sum(acc2[3][b]) + src[3 * 4 + b] + xn[b][3];
                float si = 1.f / (1.f + __expf(-gi));
                float sf = 1.f / (1.f + __expf(-gf));
                float so = 1.f / (1.f + __expf(-go));
                float tg = tanhf(gg);
                float cn = sf * c[b] + si * tg;
                c[b] = cn;
                float hn = so * tanhf(cn);
                if (step < 41) {
                    unsigned eoff = woff + (unsigned)(rloc * 128 + u) * 4u;
#pragma unroll
                    for (int r = 0; r < 4; r++)
                        asm volatile("st.shared::cluster.f32 [%0], %1;"
                                     :: "r"(rb[r] + eoff), "f"(hn) : "memory");
                }
                if (step >= 32) g_hdec[step - 32][(b0 + rloc) * 128 + u] = hn;
            }
        }

        if (step < 41) {
            asm volatile("barrier.cluster.arrive.aligned;" ::: "memory");
            if (kh == 0) {
                if (step + 1 < 32) {
#pragma unroll
                    for (int b = 0; b < 4; b++) {
                        const float* xr = g_xg + ((long)(b0 + tr + 8 * b) * 32 + (step + 1)) * 512;
#pragma unroll
                        for (int a = 0; a < 4; a++) xn[b][a] = xr[a * 128 + u];
                    }
                } else {
#pragma unroll
                    for (int b = 0; b < 4; b++)
#pragma unroll
                        for (int a = 0; a < 4; a++) xn[b][a] = db[a];
                }
            }
            asm volatile("barrier.cluster.wait.aligned;" ::: "memory");
            pread ^= 1;
        }
    }

    asm volatile("barrier.cluster.arrive.aligned;" ::: "memory");
    asm volatile("barrier.cluster.wait.aligned;" ::: "memory");
}

// ---------------- output head ----------------
__global__ void head_kernel(const float* __restrict__ ow, const float* __restrict__ ob,
                            float* __restrict__ out)
{
    __shared__ float hsm[64 * 129];
    __shared__ float wsm[12 * 129];
    __shared__ float bsm[12];
    int tid = threadIdx.x;
    int s = blockIdx.y, b0 = blockIdx.x * 64;
    for (int i = tid; i < 64 * 128; i += 256) {
        int r = i >> 7, k = i & 127;
        hsm[r * 129 + k] = g_hdec[s][(b0 + r) * 128 + k];
    }
    for (int i = tid; i < 12 * 128; i += 256) {
        int r = i / 128, k = i % 128;
        wsm[r * 129 + k] = ow[i];
    }
    if (tid < 12) bsm[tid] = ob[tid];
    __syncthreads();
    for (int it = tid; it < 64 * 12; it += 256) {
        int b = it / 12, v = it % 12;
        float acc = bsm[v];
        for (int k = 0; k < 128; k++) acc += hsm[b * 129 + k] * wsm[v * 129 + k];
        out[(long)(b0 + b) * 120 + s * 12 + v] = acc;
    }
}

// ---------------- launcher ----------------
extern "C" void kernel_launch(void* const* d_in, const int* in_sizes, int n_in,
                              void* d_out, int out_size)
{
    const float* obs    = (const float*)d_in[0];
    const float* c1w    = (const float*)d_in[1];
    const float* c1b    = (const float*)d_in[2];
    const float* c2w    = (const float*)d_in[3];
    const float* c2b    = (const float*)d_in[4];
    const float* fc1w   = (const float*)d_in[5];
    const float* fc1b   = (const float*)d_in[6];
    const float* bn1g   = (const float*)d_in[7];
    const float* bn1b   = (const float*)d_in[8];
    const float* bn1m   = (const float*)d_in[9];
    const float* bn1v   = (const float*)d_in[10];
    const float* fc2w   = (const float*)d_in[11];
    const float* fc2b   = (const float*)d_in[12];
    const float* bn2g   = (const float*)d_in[13];
    const float* bn2b   = (const float*)d_in[14];
    const float* bn2m   = (const float*)d_in[15];
    const float* bn2v   = (const float*)d_in[16];
    const float* encwih = (const float*)d_in[17];
    const float* encwhh = (const float*)d_in[18];
    const float* encb   = (const float*)d_in[19];
    const float* decwih = (const float*)d_in[20];
    const float* decwhh = (const float*)d_in[21];
    const float* decb   = (const float*)d_in[22];
    const float* outw   = (const float*)d_in[23];
    const float* outb   = (const float*)d_in[24];
    float* out = (float*)d_out;

    const int fc_smem    = (128 * WPAD + 64 * WPAD + 64 * 128 * 2) * 4;
    const int xproj_smem = (128 * 64 + 128 * BPAD) * 4;
    const int lstm_smem  = (2 * 128 * WPAD + 2 * 32 * 128 + 256 * SRSTRIDE) * 4;
    cudaFuncSetAttribute(fc_kernel, cudaFuncAttributeMaxDynamicSharedMemorySize, fc_smem);
    cudaFuncSetAttribute(xproj_kernel, cudaFuncAttributeMaxDynamicSharedMemorySize, xproj_smem);
    cudaFuncSetAttribute(lstm_persistent, cudaFuncAttributeMaxDynamicSharedMemorySize, lstm_smem);

    cnn_kernel<<<CNN_GRID, 128>>>(obs, c1w, c1b, c2w, c2b);
    fc_kernel<<<FC_GRID, 256, fc_smem>>>(fc1w, fc1b, bn1g, bn1b, bn1m, bn1v,
                                         fc2w, fc2b, bn2g, bn2b, bn2m, bn2v);
    xproj_kernel<<<XP_GROUPS * 4, 512, xproj_smem>>>(encwih, encb);

    lstm_persistent<<<128, 512, lstm_smem>>>(encwhh, decwih, decwhh, decb);

    dim3 hgrid(16, 10);
    head_kernel<<<hgrid, 256>>>(outw, outb, out);
}